// round 15
// baseline (speedup 1.0000x reference)
#include <cuda_runtime.h>
#include <math.h>
#include <stdint.h>

#define NN 50000
#define NE 800000
#define IN_DIM 64
#define HID 128
#define NLAYERS 4
#define TS 64               // edges per block in edge MLP
#define NTILES (NE / TS)    // 12500

// Persistent scratch (no allocations allowed)
__device__ float g_h[NN * HID];       // node embeddings
__device__ float g_mean[NN * HID];    // neighbor-mean
__device__ float g_pu[NN * HID];      // h @ W0_top + b0
__device__ float g_pv[NN * HID];      // h @ W0_bot
__device__ int   g_cnt[NN];           // histogram / fill counters
__device__ int   g_row[NN + 1];       // CSR row offsets (by dst)
__device__ int   g_csr_src[NE];       // src node per CSR slot

// ---------------------------------------------------------------------------
__device__ __forceinline__ uint32_t f2tf(float x) {
    uint32_t r;
    asm("cvt.rna.tf32.f32 %0, %1;" : "=r"(r) : "f"(x));
    return r;
}

__device__ __forceinline__ void mma_tf32(float* c, uint32_t a0, uint32_t a1,
                                         uint32_t a2, uint32_t a3,
                                         uint32_t b0, uint32_t b1) {
    asm volatile(
        "mma.sync.aligned.m16n8k8.row.col.f32.tf32.tf32.f32 "
        "{%0,%1,%2,%3}, {%4,%5,%6,%7}, {%8,%9}, {%0,%1,%2,%3};\n"
        : "+f"(c[0]), "+f"(c[1]), "+f"(c[2]), "+f"(c[3])
        : "r"(a0), "r"(a1), "r"(a2), "r"(a3), "r"(b0), "r"(b1));
}

// ---------------------------------------------------------------------------
__global__ void __launch_bounds__(256) zero_cnt_kernel() {
    int i = blockIdx.x * blockDim.x + threadIdx.x;
    if (i < NN) g_cnt[i] = 0;
}

__global__ void __launch_bounds__(256) hist_kernel(const int* __restrict__ dst) {
    int e = blockIdx.x * blockDim.x + threadIdx.x;
    if (e < NE) atomicAdd(&g_cnt[dst[e]], 1);
}

// single-block exclusive scan of g_cnt -> g_row; re-zeroes g_cnt for the fill
__global__ void __launch_bounds__(1024) scan_kernel() {
    __shared__ int sh[1024];
    const int CH = (NN + 1023) / 1024;  // 49
    int t = threadIdx.x;
    int base = t * CH;
    int s = 0;
    for (int j = 0; j < CH; j++) {
        int idx = base + j;
        if (idx < NN) s += g_cnt[idx];
    }
    sh[t] = s;
    __syncthreads();
    for (int off = 1; off < 1024; off <<= 1) {
        int u = sh[t];
        if (t >= off) u += sh[t - off];
        __syncthreads();
        sh[t] = u;
        __syncthreads();
    }
    int run = (t == 0) ? 0 : sh[t - 1];
    for (int j = 0; j < CH; j++) {
        int idx = base + j;
        if (idx < NN) {
            g_row[idx] = run;
            run += g_cnt[idx];
            g_cnt[idx] = 0;
        }
    }
    if (t == 1023) g_row[NN] = NE;
}

__global__ void __launch_bounds__(256) fill_kernel(const int* __restrict__ src,
                                                   const int* __restrict__ dst) {
    int e = blockIdx.x * blockDim.x + threadIdx.x;
    if (e >= NE) return;
    int d = dst[e];
    int pos = g_row[d] + atomicAdd(&g_cnt[d], 1);
    g_csr_src[pos] = src[e];
}

// ---------------------------------------------------------------------------
// warp per node: mean of neighbor rows. Indices fetched 32-at-a-time via one
// coalesced LDG + shfl broadcast (halves LDG issue count); rows 4-deep MLP.
__global__ void __launch_bounds__(256) agg_kernel() {
    int w = (blockIdx.x * 256 + threadIdx.x) >> 5;
    int lane = threadIdx.x & 31;
    if (w >= NN) return;
    int s0 = g_row[w], s1 = g_row[w + 1];
    float4 a = {0.f, 0.f, 0.f, 0.f};
    float4 b = {0.f, 0.f, 0.f, 0.f};
    float4 c = {0.f, 0.f, 0.f, 0.f};
    float4 d = {0.f, 0.f, 0.f, 0.f};
    for (int base = s0; base < s1; base += 32) {
        int n = s1 - base;
        int lim = (n < 32) ? n : 32;
        int myidx = 0;
        if (lane < lim) myidx = __ldg(&g_csr_src[base + lane]);
        int j = 0;
        for (; j + 3 < lim; j += 4) {
            int na = __shfl_sync(0xffffffffu, myidx, j);
            int nb = __shfl_sync(0xffffffffu, myidx, j + 1);
            int nc = __shfl_sync(0xffffffffu, myidx, j + 2);
            int nd = __shfl_sync(0xffffffffu, myidx, j + 3);
            float4 va = *reinterpret_cast<const float4*>(&g_h[na * HID + lane * 4]);
            float4 vb = *reinterpret_cast<const float4*>(&g_h[nb * HID + lane * 4]);
            float4 vc = *reinterpret_cast<const float4*>(&g_h[nc * HID + lane * 4]);
            float4 vd = *reinterpret_cast<const float4*>(&g_h[nd * HID + lane * 4]);
            a.x += va.x; a.y += va.y; a.z += va.z; a.w += va.w;
            b.x += vb.x; b.y += vb.y; b.z += vb.z; b.w += vb.w;
            c.x += vc.x; c.y += vc.y; c.z += vc.z; c.w += vc.w;
            d.x += vd.x; d.y += vd.y; d.z += vd.z; d.w += vd.w;
        }
        for (; j < lim; j++) {
            int na = __shfl_sync(0xffffffffu, myidx, j);
            float4 va = *reinterpret_cast<const float4*>(&g_h[na * HID + lane * 4]);
            a.x += va.x; a.y += va.y; a.z += va.z; a.w += va.w;
        }
    }
    a.x += b.x + c.x + d.x;
    a.y += b.y + c.y + d.y;
    a.z += b.z + c.z + d.z;
    a.w += b.w + c.w + d.w;
    float inv = 1.0f / fmaxf((float)(s1 - s0), 1.0f);
    float4 o = {a.x * inv, a.y * inv, a.z * inv, a.w * inv};
    *reinterpret_cast<float4*>(&g_mean[w * HID + lane * 4]) = o;
}

// ---------------------------------------------------------------------------
// embed via tf32 mma: h = x @ W_embed + b  (K=64, N=128), 64 rows/block.
#define EM_A    0                          // [64][68] tf32
#define EM_BT   (64 * 68)                  // [128][69] tf32
#define EM_BIAS (EM_BT + 128 * 69)
#define EM_FLOATS (EM_BIAS + 128)
#define EM_BYTES (EM_FLOATS * 4)

__global__ void __launch_bounds__(256) embed_kernel(const float* __restrict__ x,
                                                    const float* __restrict__ W,
                                                    const float* __restrict__ b) {
    extern __shared__ float sm_em[];
    uint32_t* A_s  = (uint32_t*)(sm_em + EM_A);
    uint32_t* Bt   = (uint32_t*)(sm_em + EM_BT);
    float*    bias = sm_em + EM_BIAS;

    int tid = threadIdx.x;
    int w = tid >> 5, lane = tid & 31;
    int g = lane >> 2, tig = lane & 3;
    int rg = w & 3, r0 = rg * 16;
    int ch = w >> 2, n0 = ch * 64;
    int row0 = blockIdx.x * 64;

    if (tid < 128) bias[tid] = b[tid];

#pragma unroll
    for (int i = 0; i < 16; i++) {
        int idx = tid + i * 256;
        int r = idx >> 6, k = idx & 63;
        int row = row0 + r;
        A_s[r * 68 + k] = f2tf((row < NN) ? x[row * IN_DIM + k] : 0.0f);
    }
    {
        int c = tid & 127, kb = tid >> 7;
#pragma unroll
        for (int j = 0; j < 32; j++) {
            int k = kb * 32 + j;
            Bt[c * 69 + k] = f2tf(W[k * HID + c]);
        }
    }
    __syncthreads();

    float C[8][4];
#pragma unroll
    for (int nt = 0; nt < 8; nt++)
#pragma unroll
        for (int j = 0; j < 4; j++) C[nt][j] = 0.0f;

#pragma unroll
    for (int s = 0; s < 8; s++) {
        int kl = s * 8;
        uint32_t a0 = A_s[(r0 + g) * 68 + kl + tig];
        uint32_t a1 = A_s[(r0 + g + 8) * 68 + kl + tig];
        uint32_t a2 = A_s[(r0 + g) * 68 + kl + tig + 4];
        uint32_t a3 = A_s[(r0 + g + 8) * 68 + kl + tig + 4];
#pragma unroll
        for (int nt = 0; nt < 8; nt++) {
            int nn = n0 + nt * 8 + g;
            uint32_t b0 = Bt[nn * 69 + kl + tig];
            uint32_t b1 = Bt[nn * 69 + kl + tig + 4];
            mma_tf32(C[nt], a0, a1, a2, a3, b0, b1);
        }
    }

    int grow0 = row0 + r0 + g;
    int grow1 = grow0 + 8;
    if (grow0 < NN)
#pragma unroll
        for (int nt = 0; nt < 8; nt++) {
            int col = n0 + nt * 8 + 2 * tig;
            float2 o = {C[nt][0] + bias[col], C[nt][1] + bias[col + 1]};
            *reinterpret_cast<float2*>(&g_h[grow0 * HID + col]) = o;
        }
    if (grow1 < NN)
#pragma unroll
        for (int nt = 0; nt < 8; nt++) {
            int col = n0 + nt * 8 + 2 * tig;
            float2 o = {C[nt][2] + bias[col], C[nt][3] + bias[col + 1]};
            *reinterpret_cast<float2*>(&g_h[grow1 * HID + col]) = o;
        }
}

// ---------------------------------------------------------------------------
// node_apply via tf32 mma: 128 rows/block, 512 threads (16 warps), 3 CTAs/SM.
// warp w: rg = w&7 -> rows rg*16..rg*16+15 ; ch = w>>3 -> cols ch*64..ch*64+63
#define NA_A    0                          // [128][68] u32
#define NA_BT   (128 * 68)                 // [128][69] u32
#define NA_RQ   (NA_BT + 128 * 69)         // [2][128]
#define NA_BIAS (NA_RQ + 256)
#define NA_FLOATS (NA_BIAS + 128)
#define NA_BYTES (NA_FLOATS * 4)

__global__ void __launch_bounds__(512) node_apply_kernel(const float* __restrict__ Wc,
                                                         const float* __restrict__ bc,
                                                         int layer) {
    extern __shared__ float sm_na[];
    uint32_t* A_s  = (uint32_t*)(sm_na + NA_A);
    uint32_t* Bt   = (uint32_t*)(sm_na + NA_BT);
    float*    rowsq = sm_na + NA_RQ;
    float*    bias  = sm_na + NA_BIAS;

    const float* W = Wc + layer * (2 * HID) * HID;
    const float* b = bc + layer * HID;

    int tid = threadIdx.x;
    int w = tid >> 5, lane = tid & 31;
    int g = lane >> 2, tig = lane & 3;
    int rg = w & 7, r0 = rg * 16;
    int ch = w >> 3, n0 = ch * 64;
    int row0 = blockIdx.x * 128;

    if (tid < 128) bias[tid] = b[tid];

    float C[8][4];
#pragma unroll
    for (int nt = 0; nt < 8; nt++)
#pragma unroll
        for (int j = 0; j < 4; j++) C[nt][j] = 0.0f;

    for (int kk = 0; kk < 2 * HID; kk += 64) {
        __syncthreads();
        // A: 128 rows x 64 k (tf32)
#pragma unroll
        for (int i = 0; i < 16; i++) {
            int idx = tid + i * 512;
            int r = idx >> 6, k = idx & 63;
            int gk = kk + k;
            int row = row0 + r;
            float v = 0.0f;
            if (row < NN)
                v = (gk < HID) ? g_h[row * HID + gk] : g_mean[row * HID + gk - HID];
            A_s[r * 68 + k] = f2tf(v);
        }
        // Bt: [n=128][k=64]
        {
            int c = tid & 127, kb = tid >> 7;   // kb 0..3
#pragma unroll
            for (int j = 0; j < 16; j++) {
                int k = kb * 16 + j;
                Bt[c * 69 + k] = f2tf(W[(kk + k) * HID + c]);
            }
        }
        __syncthreads();

#pragma unroll
        for (int s = 0; s < 8; s++) {
            int kl = s * 8;
            uint32_t a0 = A_s[(r0 + g) * 68 + kl + tig];
            uint32_t a1 = A_s[(r0 + g + 8) * 68 + kl + tig];
            uint32_t a2 = A_s[(r0 + g) * 68 + kl + tig + 4];
            uint32_t a3 = A_s[(r0 + g + 8) * 68 + kl + tig + 4];
#pragma unroll
            for (int nt = 0; nt < 8; nt++) {
                int nn = n0 + nt * 8 + g;
                uint32_t b0 = Bt[nn * 69 + kl + tig];
                uint32_t b1 = Bt[nn * 69 + kl + tig + 4];
                mma_tf32(C[nt], a0, a1, a2, a3, b0, b1);
            }
        }
    }

    float ss0 = 0.0f, ss1 = 0.0f;
#pragma unroll
    for (int nt = 0; nt < 8; nt++) {
        int col = n0 + nt * 8 + 2 * tig;
        C[nt][0] += bias[col];
        C[nt][1] += bias[col + 1];
        C[nt][2] += bias[col];
        C[nt][3] += bias[col + 1];
        ss0 += C[nt][0] * C[nt][0] + C[nt][1] * C[nt][1];
        ss1 += C[nt][2] * C[nt][2] + C[nt][3] * C[nt][3];
    }
    ss0 += __shfl_xor_sync(0xffffffffu, ss0, 1);
    ss0 += __shfl_xor_sync(0xffffffffu, ss0, 2);
    ss1 += __shfl_xor_sync(0xffffffffu, ss1, 1);
    ss1 += __shfl_xor_sync(0xffffffffu, ss1, 2);
    if (tig == 0) {
        rowsq[ch * 128 + r0 + g] = ss0;
        rowsq[ch * 128 + r0 + g + 8] = ss1;
    }
    __syncthreads();
    float t0 = rowsq[r0 + g] + rowsq[128 + r0 + g];
    float t1 = rowsq[r0 + g + 8] + rowsq[128 + r0 + g + 8];
    float inv0 = 1.0f / fmaxf(sqrtf(t0), 1e-12f);
    float inv1 = 1.0f / fmaxf(sqrtf(t1), 1e-12f);

    int grow0 = row0 + r0 + g;
    int grow1 = grow0 + 8;
    if (grow0 < NN) {
#pragma unroll
        for (int nt = 0; nt < 8; nt++) {
            int col = n0 + nt * 8 + 2 * tig;
            float2 old = *reinterpret_cast<float2*>(&g_h[grow0 * HID + col]);
            old.x += fmaxf(C[nt][0] * inv0, 0.0f);
            old.y += fmaxf(C[nt][1] * inv0, 0.0f);
            *reinterpret_cast<float2*>(&g_h[grow0 * HID + col]) = old;
        }
    }
    if (grow1 < NN) {
#pragma unroll
        for (int nt = 0; nt < 8; nt++) {
            int col = n0 + nt * 8 + 2 * tig;
            float2 old = *reinterpret_cast<float2*>(&g_h[grow1 * HID + col]);
            old.x += fmaxf(C[nt][2] * inv1, 0.0f);
            old.y += fmaxf(C[nt][3] * inv1, 0.0f);
            *reinterpret_cast<float2*>(&g_h[grow1 * HID + col]) = old;
        }
    }
}

// ---------------------------------------------------------------------------
// pre_edge via tf32 mma: pu = h @ W0[0:128,:] + b0 ; pv = h @ W0[128:256,:]
#define PE_A    0                          // [64][132] tf32
#define PE_BT   (64 * 132)                 // [128][69] tf32
#define PE_BIAS (PE_BT + 128 * 69)
#define PE_FLOATS (PE_BIAS + 128)
#define PE_BYTES (PE_FLOATS * 4)

__global__ void __launch_bounds__(256) pre_edge_kernel(const float* __restrict__ W0,
                                                       const float* __restrict__ b0) {
    extern __shared__ float sm_pe[];
    uint32_t* A_s  = (uint32_t*)(sm_pe + PE_A);
    uint32_t* Bt   = (uint32_t*)(sm_pe + PE_BT);
    float*    bias = sm_pe + PE_BIAS;

    int tid = threadIdx.x;
    int w = tid >> 5, lane = tid & 31;
    int g = lane >> 2, tig = lane & 3;
    int rg = w & 3, r0 = rg * 16;
    int ch = w >> 2, n0 = ch * 64;
    int row0 = blockIdx.x * 64;

    if (tid < 128) bias[tid] = b0[tid];

#pragma unroll
    for (int i = 0; i < 32; i++) {
        int idx = tid + i * 256;
        int r = idx >> 7, k = idx & 127;
        int row = row0 + r;
        A_s[r * 132 + k] = f2tf((row < NN) ? g_h[row * HID + k] : 0.0f);
    }

#pragma unroll
    for (int half = 0; half < 2; half++) {
        float C[8][4];
#pragma unroll
        for (int nt = 0; nt < 8; nt++)
#pragma unroll
            for (int j = 0; j < 4; j++) C[nt][j] = 0.0f;

        for (int kk = 0; kk < HID; kk += 64) {
            __syncthreads();
            {
                int c = tid & 127, kb = tid >> 7;
#pragma unroll
                for (int j = 0; j < 32; j++) {
                    int k = kb * 32 + j;
                    Bt[c * 69 + k] = f2tf(W0[(half * HID + kk + k) * HID + c]);
                }
            }
            __syncthreads();
#pragma unroll
            for (int s = 0; s < 8; s++) {
                int kl = s * 8;
                uint32_t a0 = A_s[(r0 + g) * 132 + kk + kl + tig];
                uint32_t a1 = A_s[(r0 + g + 8) * 132 + kk + kl + tig];
                uint32_t a2 = A_s[(r0 + g) * 132 + kk + kl + tig + 4];
                uint32_t a3 = A_s[(r0 + g + 8) * 132 + kk + kl + tig + 4];
#pragma unroll
                for (int nt = 0; nt < 8; nt++) {
                    int nn = n0 + nt * 8 + g;
                    uint32_t b0r = Bt[nn * 69 + kl + tig];
                    uint32_t b1r = Bt[nn * 69 + kl + tig + 4];
                    mma_tf32(C[nt], a0, a1, a2, a3, b0r, b1r);
                }
            }
        }

        int grow0 = row0 + r0 + g;
        int grow1 = grow0 + 8;
        if (half == 0) {
            if (grow0 < NN)
#pragma unroll
                for (int nt = 0; nt < 8; nt++) {
                    int col = n0 + nt * 8 + 2 * tig;
                    float2 o = {C[nt][0] + bias[col], C[nt][1] + bias[col + 1]};
                    *reinterpret_cast<float2*>(&g_pu[grow0 * HID + col]) = o;
                }
            if (grow1 < NN)
#pragma unroll
                for (int nt = 0; nt < 8; nt++) {
                    int col = n0 + nt * 8 + 2 * tig;
                    float2 o = {C[nt][2] + bias[col], C[nt][3] + bias[col + 1]};
                    *reinterpret_cast<float2*>(&g_pu[grow1 * HID + col]) = o;
                }
        } else {
            if (grow0 < NN)
#pragma unroll
                for (int nt = 0; nt < 8; nt++) {
                    int col = n0 + nt * 8 + 2 * tig;
                    float2 o = {C[nt][0], C[nt][1]};
                    *reinterpret_cast<float2*>(&g_pv[grow0 * HID + col]) = o;
                }
            if (grow1 < NN)
#pragma unroll
                for (int nt = 0; nt < 8; nt++) {
                    int col = n0 + nt * 8 + 2 * tig;
                    float2 o = {C[nt][2], C[nt][3]};
                    *reinterpret_cast<float2*>(&g_pv[grow1 * HID + col]) = o;
                }
        }
    }
}

// ---------------------------------------------------------------------------
// Edge readout: e1 = relu(pu[src]+pv[dst]) (tf32); e2 = relu(e1 @ W1 + b1)
// via tf32 mma; out = e2 @ W2 + b2. 64 edges/block, 256 threads.
#define ESM_W1T 0                           // [64 n][132 k] tf32
#define ESM_E1  (64 * 132)                  // [64][132] tf32
#define ESM_E2  (ESM_E1 + 64 * 132)         // [64][66]
#define ESM_B1  (ESM_E2 + 64 * 66)
#define ESM_W2  (ESM_B1 + 64)
#define ESM_B2  (ESM_W2 + 128)
#define ESM_IDX (ESM_B2 + 4)                // srcs[64], dsts[64]
#define SMEM_EDGE_BYTES ((ESM_IDX + 128) * 4)

__global__ void __launch_bounds__(256) edge_mlp_kernel(
        const int* __restrict__ src, const int* __restrict__ dst,
        const float* __restrict__ W1, const float* __restrict__ b1,
        const float* __restrict__ W2, const float* __restrict__ b2,
        float* __restrict__ out) {
    extern __shared__ float sm_e[];
    uint32_t* W1t = (uint32_t*)(sm_e + ESM_W1T);
    uint32_t* e1u = (uint32_t*)(sm_e + ESM_E1);
    float* e2s = sm_e + ESM_E2;
    float* b1s = sm_e + ESM_B1;
    float* W2s = sm_e + ESM_W2;
    float* b2s = sm_e + ESM_B2;
    int*   srcs = (int*)(sm_e + ESM_IDX);
    int*   dsts = srcs + 64;

    int tid = threadIdx.x;
    int e0 = blockIdx.x * TS;
    int w = tid >> 5, lane = tid & 31;
    int g = lane >> 2, tig = lane & 3;
    int rg = w & 3, r0 = rg * 16;
    int ch = w >> 2, n0 = ch * 32;

    {
        int n = tid & 63, kb = tid >> 6;
#pragma unroll
        for (int j = 0; j < 32; j++) {
            int k = kb + j * 4;
            W1t[n * 132 + k] = f2tf(W1[k * 64 + n]);
        }
    }
    if (tid < 64)  b1s[tid] = b1[tid];
    if (tid < 128) W2s[tid] = W2[tid];
    if (tid < 2)   b2s[tid] = b2[tid];
    if (tid < 64)  { srcs[tid] = src[e0 + tid]; dsts[tid] = dst[e0 + tid]; }
    __syncthreads();

    // ---- stage 1: gather + add + relu -> e1 (tf32) ----
#pragma unroll
    for (int i = 0; i < 8; i++) {
        int idx = tid + i * 256;            // float4 units, 2048 total
        int r = idx >> 5, c4 = idx & 31;
        const float4 u = *reinterpret_cast<const float4*>(&g_pu[srcs[r] * HID + c4 * 4]);
        const float4 v = *reinterpret_cast<const float4*>(&g_pv[dsts[r] * HID + c4 * 4]);
        uint4 o;
        o.x = f2tf(fmaxf(u.x + v.x, 0.0f));
        o.y = f2tf(fmaxf(u.y + v.y, 0.0f));
        o.z = f2tf(fmaxf(u.z + v.z, 0.0f));
        o.w = f2tf(fmaxf(u.w + v.w, 0.0f));
        *reinterpret_cast<uint4*>(&e1u[r * 132 + c4 * 4]) = o;
    }
    __syncthreads();

    // ---- stage 2: [64,128] @ [128,64] via tf32 mma ----
    float C[4][4];
#pragma unroll
    for (int nt = 0; nt < 4; nt++)
#pragma unroll
        for (int j = 0; j < 4; j++) C[nt][j] = 0.0f;

#pragma unroll
    for (int s = 0; s < 16; s++) {
        int kl = s * 8;
        uint32_t a0 = e1u[(r0 + g) * 132 + kl + tig];
        uint32_t a1 = e1u[(r0 + g + 8) * 132 + kl + tig];
        uint32_t a2 = e1u[(r0 + g) * 132 + kl + tig + 4];
        uint32_t a3 = e1u[(r0 + g + 8) * 132 + kl + tig + 4];
#pragma unroll
        for (int nt = 0; nt < 4; nt++) {
            int nn = n0 + nt * 8 + g;
            uint32_t b0 = W1t[nn * 132 + kl + tig];
            uint32_t b1f = W1t[nn * 132 + kl + tig + 4];
            mma_tf32(C[nt], a0, a1, a2, a3, b0, b1f);
        }
    }
#pragma unroll
    for (int nt = 0; nt < 4; nt++) {
        int col = n0 + nt * 8 + 2 * tig;
        e2s[(r0 + g) * 66 + col]     = fmaxf(C[nt][0] + b1s[col], 0.0f);
        e2s[(r0 + g) * 66 + col + 1] = fmaxf(C[nt][1] + b1s[col + 1], 0.0f);
        e2s[(r0 + g + 8) * 66 + col]     = fmaxf(C[nt][2] + b1s[col], 0.0f);
        e2s[(r0 + g + 8) * 66 + col + 1] = fmaxf(C[nt][3] + b1s[col + 1], 0.0f);
    }
    __syncthreads();

    // ---- stage 3: [64,64] @ [64,2] -> out, all 256 threads ----
    {
        int r = tid >> 2, sub = tid & 3, c = sub >> 1, kh = sub & 1;
        float s = 0.0f;
        const float* row = &e2s[r * 66 + kh * 32];
#pragma unroll
        for (int k = 0; k < 32; k++) s += row[k] * W2s[(kh * 32 + k) * 2 + c];
        s += __shfl_xor_sync(0xffffffffu, s, 1);
        if (kh == 0) out[(e0 + r) * 2 + c] = s + b2s[c];
    }
}

// ---------------------------------------------------------------------------
extern "C" void kernel_launch(void* const* d_in, const int* in_sizes, int n_in,
                              void* d_out, int out_size) {
    const float* x       = (const float*)d_in[0];
    const int*   src     = (const int*)d_in[1];
    const int*   dst     = (const int*)d_in[2];
    // d_in[3] snorm_n, d_in[4] snorm_e: all-ones, unused
    const float* W_embed = (const float*)d_in[5];
    const float* b_embed = (const float*)d_in[6];
    const float* W_conv  = (const float*)d_in[7];
    const float* b_conv  = (const float*)d_in[8];
    const float* W0      = (const float*)d_in[9];
    const float* b0      = (const float*)d_in[10];
    const float* W1      = (const float*)d_in[11];
    const float* b1      = (const float*)d_in[12];
    const float* W2      = (const float*)d_in[13];
    const float* b2      = (const float*)d_in[14];
    float* out = (float*)d_out;

    cudaFuncSetAttribute(edge_mlp_kernel,
                         cudaFuncAttributeMaxDynamicSharedMemorySize,
                         SMEM_EDGE_BYTES);
    cudaFuncSetAttribute(node_apply_kernel,
                         cudaFuncAttributeMaxDynamicSharedMemorySize,
                         NA_BYTES);
    cudaFuncSetAttribute(pre_edge_kernel,
                         cudaFuncAttributeMaxDynamicSharedMemorySize,
                         PE_BYTES);
    cudaFuncSetAttribute(embed_kernel,
                         cudaFuncAttributeMaxDynamicSharedMemorySize,
                         EM_BYTES);

    // CSR build (by dst)
    zero_cnt_kernel<<<(NN + 255) / 256, 256>>>();
    hist_kernel<<<(NE + 255) / 256, 256>>>(dst);
    scan_kernel<<<1, 1024>>>();
    fill_kernel<<<(NE + 255) / 256, 256>>>(src, dst);

    embed_kernel<<<(NN + 63) / 64, 256, EM_BYTES>>>(x, W_embed, b_embed);

    for (int l = 0; l < NLAYERS; l++) {
        agg_kernel<<<(NN * 32 + 255) / 256, 256>>>();
        node_apply_kernel<<<(NN + 127) / 128, 512, NA_BYTES>>>(W_conv, b_conv, l);
    }

    pre_edge_kernel<<<(NN + 63) / 64, 256, PE_BYTES>>>(W0, b0);
    edge_mlp_kernel<<<NTILES, 256, SMEM_EDGE_BYTES>>>(src, dst, W1, b1, W2, b2,
                                                      out);
}

// round 16
// speedup vs baseline: 1.0540x; 1.0540x over previous
#include <cuda_runtime.h>
#include <math.h>
#include <stdint.h>

#define NN 50000
#define NE 800000
#define IN_DIM 64
#define HID 128
#define NLAYERS 4
#define TS 64               // edges per block in edge MLP
#define NTILES (NE / TS)    // 12500
#define NSBLK ((NN + 255) / 256)   // 196 scan blocks

// Persistent scratch (no allocations allowed)
__device__ float g_h[NN * HID];       // node embeddings
__device__ float g_mean[NN * HID];    // neighbor-mean
__device__ float g_pu[NN * HID];      // h @ W0_top + b0
__device__ float g_pv[NN * HID];      // h @ W0_bot
__device__ int   g_cnt[NN];           // histogram / fill counters
__device__ int   g_row[NN + 1];       // CSR row offsets (by dst)
__device__ int   g_csr_src[NE];       // src node per CSR slot
__device__ int   g_bsum[NSBLK];       // scan block sums

// ---------------------------------------------------------------------------
__device__ __forceinline__ uint32_t f2tf(float x) {
    uint32_t r;
    asm("cvt.rna.tf32.f32 %0, %1;" : "=r"(r) : "f"(x));
    return r;
}

// fragment permutation: puts (k+tig, k+tig+4) adjacent for paired LDS.64
__device__ __forceinline__ int kperm(int k) {
    return (k & ~7) + ((k & 3) << 1) + ((k >> 2) & 1);
}

__device__ __forceinline__ void mma_tf32(float* c, uint32_t a0, uint32_t a1,
                                         uint32_t a2, uint32_t a3,
                                         uint32_t b0, uint32_t b1) {
    asm volatile(
        "mma.sync.aligned.m16n8k8.row.col.f32.tf32.tf32.f32 "
        "{%0,%1,%2,%3}, {%4,%5,%6,%7}, {%8,%9}, {%0,%1,%2,%3};\n"
        : "+f"(c[0]), "+f"(c[1]), "+f"(c[2]), "+f"(c[3])
        : "r"(a0), "r"(a1), "r"(a2), "r"(a3), "r"(b0), "r"(b1));
}

// ---------------------------------------------------------------------------
__global__ void __launch_bounds__(256) zero_cnt_kernel() {
    int i = blockIdx.x * blockDim.x + threadIdx.x;
    if (i < NN) g_cnt[i] = 0;
}

__global__ void __launch_bounds__(256) hist_kernel(const int* __restrict__ dst) {
    int e = blockIdx.x * blockDim.x + threadIdx.x;
    if (e < NE) atomicAdd(&g_cnt[dst[e]], 1);
}

// parallel scan, 3 stages
__global__ void __launch_bounds__(256) scan1_kernel() {
    __shared__ int sh[256];
    int t = threadIdx.x;
    int i = blockIdx.x * 256 + t;
    sh[t] = (i < NN) ? g_cnt[i] : 0;
    __syncthreads();
    for (int off = 128; off > 0; off >>= 1) {
        if (t < off) sh[t] += sh[t + off];
        __syncthreads();
    }
    if (t == 0) g_bsum[blockIdx.x] = sh[0];
}

__global__ void __launch_bounds__(256) scan2_kernel() {
    __shared__ int sh[256];
    int t = threadIdx.x;
    sh[t] = (t < NSBLK) ? g_bsum[t] : 0;
    __syncthreads();
    for (int off = 1; off < 256; off <<= 1) {
        int u = sh[t];
        if (t >= off) u += sh[t - off];
        __syncthreads();
        sh[t] = u;
        __syncthreads();
    }
    if (t < NSBLK) g_bsum[t] = (t == 0) ? 0 : sh[t - 1];
    if (t == 0) g_row[NN] = NE;
}

__global__ void __launch_bounds__(256) scan3_kernel() {
    __shared__ int sh[256];
    int t = threadIdx.x;
    int i = blockIdx.x * 256 + t;
    int v = (i < NN) ? g_cnt[i] : 0;
    sh[t] = v;
    __syncthreads();
    for (int off = 1; off < 256; off <<= 1) {
        int u = sh[t];
        if (t >= off) u += sh[t - off];
        __syncthreads();
        sh[t] = u;
        __syncthreads();
    }
    if (i < NN) {
        g_row[i] = sh[t] - v + g_bsum[blockIdx.x];
        g_cnt[i] = 0;
    }
}

__global__ void __launch_bounds__(256) fill_kernel(const int* __restrict__ src,
                                                   const int* __restrict__ dst) {
    int e = blockIdx.x * blockDim.x + threadIdx.x;
    if (e >= NE) return;
    int d = dst[e];
    int pos = g_row[d] + atomicAdd(&g_cnt[d], 1);
    g_csr_src[pos] = src[e];
}

// ---------------------------------------------------------------------------
// warp per node: mean of neighbor rows, idx via coalesced LDG + shfl, MLP=4
__global__ void __launch_bounds__(256) agg_kernel() {
    int w = (blockIdx.x * 256 + threadIdx.x) >> 5;
    int lane = threadIdx.x & 31;
    if (w >= NN) return;
    int s0 = g_row[w], s1 = g_row[w + 1];
    float4 a = {0.f, 0.f, 0.f, 0.f};
    float4 b = {0.f, 0.f, 0.f, 0.f};
    float4 c = {0.f, 0.f, 0.f, 0.f};
    float4 d = {0.f, 0.f, 0.f, 0.f};
    for (int base = s0; base < s1; base += 32) {
        int n = s1 - base;
        int lim = (n < 32) ? n : 32;
        int myidx = 0;
        if (lane < lim) myidx = __ldg(&g_csr_src[base + lane]);
        int j = 0;
        for (; j + 3 < lim; j += 4) {
            int na = __shfl_sync(0xffffffffu, myidx, j);
            int nb = __shfl_sync(0xffffffffu, myidx, j + 1);
            int nc = __shfl_sync(0xffffffffu, myidx, j + 2);
            int nd = __shfl_sync(0xffffffffu, myidx, j + 3);
            float4 va = *reinterpret_cast<const float4*>(&g_h[na * HID + lane * 4]);
            float4 vb = *reinterpret_cast<const float4*>(&g_h[nb * HID + lane * 4]);
            float4 vc = *reinterpret_cast<const float4*>(&g_h[nc * HID + lane * 4]);
            float4 vd = *reinterpret_cast<const float4*>(&g_h[nd * HID + lane * 4]);
            a.x += va.x; a.y += va.y; a.z += va.z; a.w += va.w;
            b.x += vb.x; b.y += vb.y; b.z += vb.z; b.w += vb.w;
            c.x += vc.x; c.y += vc.y; c.z += vc.z; c.w += vc.w;
            d.x += vd.x; d.y += vd.y; d.z += vd.z; d.w += vd.w;
        }
        for (; j < lim; j++) {
            int na = __shfl_sync(0xffffffffu, myidx, j);
            float4 va = *reinterpret_cast<const float4*>(&g_h[na * HID + lane * 4]);
            a.x += va.x; a.y += va.y; a.z += va.z; a.w += va.w;
        }
    }
    a.x += b.x + c.x + d.x;
    a.y += b.y + c.y + d.y;
    a.z += b.z + c.z + d.z;
    a.w += b.w + c.w + d.w;
    float inv = 1.0f / fmaxf((float)(s1 - s0), 1.0f);
    float4 o = {a.x * inv, a.y * inv, a.z * inv, a.w * inv};
    *reinterpret_cast<float4*>(&g_mean[w * HID + lane * 4]) = o;
}

// ---------------------------------------------------------------------------
// embed via tf32 mma (paired-LDS layout): h = x @ W_embed + b, 64 rows/block.
#define EM_A    0                          // [64][72] tf32 (kperm)
#define EM_BT   (64 * 72)                  // [128][72] tf32 (kperm)
#define EM_BIAS (EM_BT + 128 * 72)
#define EM_FLOATS (EM_BIAS + 128)
#define EM_BYTES (EM_FLOATS * 4)

__global__ void __launch_bounds__(256) embed_kernel(const float* __restrict__ x,
                                                    const float* __restrict__ W,
                                                    const float* __restrict__ b) {
    extern __shared__ float sm_em[];
    uint32_t* A_s  = (uint32_t*)(sm_em + EM_A);
    uint32_t* Bt   = (uint32_t*)(sm_em + EM_BT);
    float*    bias = sm_em + EM_BIAS;

    int tid = threadIdx.x;
    int w = tid >> 5, lane = tid & 31;
    int g = lane >> 2, tig = lane & 3;
    int rg = w & 3, r0 = rg * 16;
    int ch = w >> 2, n0 = ch * 64;
    int row0 = blockIdx.x * 64;

    if (tid < 128) bias[tid] = b[tid];

#pragma unroll
    for (int i = 0; i < 16; i++) {
        int idx = tid + i * 256;
        int r = idx >> 6, k = idx & 63;
        int row = row0 + r;
        A_s[r * 72 + kperm(k)] = f2tf((row < NN) ? x[row * IN_DIM + k] : 0.0f);
    }
    {
        int c = tid & 127, kb = tid >> 7;
#pragma unroll
        for (int j = 0; j < 32; j++) {
            int k = kb * 32 + j;
            Bt[c * 72 + kperm(k)] = f2tf(W[k * HID + c]);
        }
    }
    __syncthreads();

    float C[8][4];
#pragma unroll
    for (int nt = 0; nt < 8; nt++)
#pragma unroll
        for (int j = 0; j < 4; j++) C[nt][j] = 0.0f;

#pragma unroll
    for (int s = 0; s < 8; s++) {
        int kl = s * 8;
        const uint2 aA = *reinterpret_cast<const uint2*>(&A_s[(r0 + g) * 72 + kl + 2 * tig]);
        const uint2 aB = *reinterpret_cast<const uint2*>(&A_s[(r0 + g + 8) * 72 + kl + 2 * tig]);
#pragma unroll
        for (int nt = 0; nt < 8; nt++) {
            int nn = n0 + nt * 8 + g;
            const uint2 bb = *reinterpret_cast<const uint2*>(&Bt[nn * 72 + kl + 2 * tig]);
            mma_tf32(C[nt], aA.x, aB.x, aA.y, aB.y, bb.x, bb.y);
        }
    }

    int grow0 = row0 + r0 + g;
    int grow1 = grow0 + 8;
    if (grow0 < NN)
#pragma unroll
        for (int nt = 0; nt < 8; nt++) {
            int col = n0 + nt * 8 + 2 * tig;
            float2 o = {C[nt][0] + bias[col], C[nt][1] + bias[col + 1]};
            *reinterpret_cast<float2*>(&g_h[grow0 * HID + col]) = o;
        }
    if (grow1 < NN)
#pragma unroll
        for (int nt = 0; nt < 8; nt++) {
            int col = n0 + nt * 8 + 2 * tig;
            float2 o = {C[nt][2] + bias[col], C[nt][3] + bias[col + 1]};
            *reinterpret_cast<float2*>(&g_h[grow1 * HID + col]) = o;
        }
}

// ---------------------------------------------------------------------------
// node_apply via tf32 mma (paired-LDS layout): 128 rows/block, 512 threads.
#define NA_A    0                          // [128][72] u32 (kperm)
#define NA_BT   (128 * 72)                 // [128][72] u32 (kperm)
#define NA_RQ   (NA_BT + 128 * 72)         // [2][128]
#define NA_BIAS (NA_RQ + 256)
#define NA_FLOATS (NA_BIAS + 128)
#define NA_BYTES (NA_FLOATS * 4)

__global__ void __launch_bounds__(512) node_apply_kernel(const float* __restrict__ Wc,
                                                         const float* __restrict__ bc,
                                                         int layer) {
    extern __shared__ float sm_na[];
    uint32_t* A_s  = (uint32_t*)(sm_na + NA_A);
    uint32_t* Bt   = (uint32_t*)(sm_na + NA_BT);
    float*    rowsq = sm_na + NA_RQ;
    float*    bias  = sm_na + NA_BIAS;

    const float* W = Wc + layer * (2 * HID) * HID;
    const float* b = bc + layer * HID;

    int tid = threadIdx.x;
    int w = tid >> 5, lane = tid & 31;
    int g = lane >> 2, tig = lane & 3;
    int rg = w & 7, r0 = rg * 16;
    int ch = w >> 3, n0 = ch * 64;
    int row0 = blockIdx.x * 128;

    if (tid < 128) bias[tid] = b[tid];

    float C[8][4];
#pragma unroll
    for (int nt = 0; nt < 8; nt++)
#pragma unroll
        for (int j = 0; j < 4; j++) C[nt][j] = 0.0f;

    for (int kk = 0; kk < 2 * HID; kk += 64) {
        __syncthreads();
#pragma unroll
        for (int i = 0; i < 16; i++) {
            int idx = tid + i * 512;
            int r = idx >> 6, k = idx & 63;
            int gk = kk + k;
            int row = row0 + r;
            float v = 0.0f;
            if (row < NN)
                v = (gk < HID) ? g_h[row * HID + gk] : g_mean[row * HID + gk - HID];
            A_s[r * 72 + kperm(k)] = f2tf(v);
        }
        {
            int c = tid & 127, kb = tid >> 7;   // kb 0..3
#pragma unroll
            for (int j = 0; j < 16; j++) {
                int k = kb * 16 + j;
                Bt[c * 72 + kperm(k)] = f2tf(W[(kk + k) * HID + c]);
            }
        }
        __syncthreads();

#pragma unroll
        for (int s = 0; s < 8; s++) {
            int kl = s * 8;
            const uint2 aA = *reinterpret_cast<const uint2*>(&A_s[(r0 + g) * 72 + kl + 2 * tig]);
            const uint2 aB = *reinterpret_cast<const uint2*>(&A_s[(r0 + g + 8) * 72 + kl + 2 * tig]);
#pragma unroll
            for (int nt = 0; nt < 8; nt++) {
                int nn = n0 + nt * 8 + g;
                const uint2 bb = *reinterpret_cast<const uint2*>(&Bt[nn * 72 + kl + 2 * tig]);
                mma_tf32(C[nt], aA.x, aB.x, aA.y, aB.y, bb.x, bb.y);
            }
        }
    }

    float ss0 = 0.0f, ss1 = 0.0f;
#pragma unroll
    for (int nt = 0; nt < 8; nt++) {
        int col = n0 + nt * 8 + 2 * tig;
        C[nt][0] += bias[col];
        C[nt][1] += bias[col + 1];
        C[nt][2] += bias[col];
        C[nt][3] += bias[col + 1];
        ss0 += C[nt][0] * C[nt][0] + C[nt][1] * C[nt][1];
        ss1 += C[nt][2] * C[nt][2] + C[nt][3] * C[nt][3];
    }
    ss0 += __shfl_xor_sync(0xffffffffu, ss0, 1);
    ss0 += __shfl_xor_sync(0xffffffffu, ss0, 2);
    ss1 += __shfl_xor_sync(0xffffffffu, ss1, 1);
    ss1 += __shfl_xor_sync(0xffffffffu, ss1, 2);
    if (tig == 0) {
        rowsq[ch * 128 + r0 + g] = ss0;
        rowsq[ch * 128 + r0 + g + 8] = ss1;
    }
    __syncthreads();
    float t0 = rowsq[r0 + g] + rowsq[128 + r0 + g];
    float t1 = rowsq[r0 + g + 8] + rowsq[128 + r0 + g + 8];
    float inv0 = 1.0f / fmaxf(sqrtf(t0), 1e-12f);
    float inv1 = 1.0f / fmaxf(sqrtf(t1), 1e-12f);

    int grow0 = row0 + r0 + g;
    int grow1 = grow0 + 8;
    if (grow0 < NN) {
#pragma unroll
        for (int nt = 0; nt < 8; nt++) {
            int col = n0 + nt * 8 + 2 * tig;
            float2 old = *reinterpret_cast<float2*>(&g_h[grow0 * HID + col]);
            old.x += fmaxf(C[nt][0] * inv0, 0.0f);
            old.y += fmaxf(C[nt][1] * inv0, 0.0f);
            *reinterpret_cast<float2*>(&g_h[grow0 * HID + col]) = old;
        }
    }
    if (grow1 < NN) {
#pragma unroll
        for (int nt = 0; nt < 8; nt++) {
            int col = n0 + nt * 8 + 2 * tig;
            float2 old = *reinterpret_cast<float2*>(&g_h[grow1 * HID + col]);
            old.x += fmaxf(C[nt][2] * inv1, 0.0f);
            old.y += fmaxf(C[nt][3] * inv1, 0.0f);
            *reinterpret_cast<float2*>(&g_h[grow1 * HID + col]) = old;
        }
    }
}

// ---------------------------------------------------------------------------
// pre_edge via tf32 mma (paired-LDS layout)
#define PE_A    0                          // [64][136] tf32 (kperm in 8-groups)
#define PE_BT   (64 * 136)                 // [128][72] tf32 (kperm)
#define PE_BIAS (PE_BT + 128 * 72)
#define PE_FLOATS (PE_BIAS + 128)
#define PE_BYTES (PE_FLOATS * 4)

__global__ void __launch_bounds__(256) pre_edge_kernel(const float* __restrict__ W0,
                                                       const float* __restrict__ b0) {
    extern __shared__ float sm_pe[];
    uint32_t* A_s  = (uint32_t*)(sm_pe + PE_A);
    uint32_t* Bt   = (uint32_t*)(sm_pe + PE_BT);
    float*    bias = sm_pe + PE_BIAS;

    int tid = threadIdx.x;
    int w = tid >> 5, lane = tid & 31;
    int g = lane >> 2, tig = lane & 3;
    int rg = w & 3, r0 = rg * 16;
    int ch = w >> 2, n0 = ch * 64;
    int row0 = blockIdx.x * 64;

    if (tid < 128) bias[tid] = b0[tid];

#pragma unroll
    for (int i = 0; i < 32; i++) {
        int idx = tid + i * 256;
        int r = idx >> 7, k = idx & 127;
        int row = row0 + r;
        A_s[r * 136 + kperm(k)] = f2tf((row < NN) ? g_h[row * HID + k] : 0.0f);
    }

#pragma unroll
    for (int half = 0; half < 2; half++) {
        float C[8][4];
#pragma unroll
        for (int nt = 0; nt < 8; nt++)
#pragma unroll
            for (int j = 0; j < 4; j++) C[nt][j] = 0.0f;

        for (int kk = 0; kk < HID; kk += 64) {
            __syncthreads();
            {
                int c = tid & 127, kb = tid >> 7;
#pragma unroll
                for (int j = 0; j < 32; j++) {
                    int k = kb * 32 + j;
                    Bt[c * 72 + kperm(k)] = f2tf(W0[(half * HID + kk + k) * HID + c]);
                }
            }
            __syncthreads();
#pragma unroll
            for (int s = 0; s < 8; s++) {
                int kl = s * 8;
                const uint2 aA = *reinterpret_cast<const uint2*>(
                    &A_s[(r0 + g) * 136 + kk + kl + 2 * tig]);
                const uint2 aB = *reinterpret_cast<const uint2*>(
                    &A_s[(r0 + g + 8) * 136 + kk + kl + 2 * tig]);
#pragma unroll
                for (int nt = 0; nt < 8; nt++) {
                    int nn = n0 + nt * 8 + g;
                    const uint2 bb = *reinterpret_cast<const uint2*>(
                        &Bt[nn * 72 + kl + 2 * tig]);
                    mma_tf32(C[nt], aA.x, aB.x, aA.y, aB.y, bb.x, bb.y);
                }
            }
        }

        int grow0 = row0 + r0 + g;
        int grow1 = grow0 + 8;
        if (half == 0) {
            if (grow0 < NN)
#pragma unroll
                for (int nt = 0; nt < 8; nt++) {
                    int col = n0 + nt * 8 + 2 * tig;
                    float2 o = {C[nt][0] + bias[col], C[nt][1] + bias[col + 1]};
                    *reinterpret_cast<float2*>(&g_pu[grow0 * HID + col]) = o;
                }
            if (grow1 < NN)
#pragma unroll
                for (int nt = 0; nt < 8; nt++) {
                    int col = n0 + nt * 8 + 2 * tig;
                    float2 o = {C[nt][2] + bias[col], C[nt][3] + bias[col + 1]};
                    *reinterpret_cast<float2*>(&g_pu[grow1 * HID + col]) = o;
                }
        } else {
            if (grow0 < NN)
#pragma unroll
                for (int nt = 0; nt < 8; nt++) {
                    int col = n0 + nt * 8 + 2 * tig;
                    float2 o = {C[nt][0], C[nt][1]};
                    *reinterpret_cast<float2*>(&g_pv[grow0 * HID + col]) = o;
                }
            if (grow1 < NN)
#pragma unroll
                for (int nt = 0; nt < 8; nt++) {
                    int col = n0 + nt * 8 + 2 * tig;
                    float2 o = {C[nt][2], C[nt][3]};
                    *reinterpret_cast<float2*>(&g_pv[grow1 * HID + col]) = o;
                }
        }
    }
}

// ---------------------------------------------------------------------------
// Edge readout: e1 = relu(pu[src]+pv[dst]); e2 = relu(e1@W1+b1) tf32 mma;
// out = e2@W2+b2. W1t in paired layout; e1 stays linear (A scalar LDS).
#define ESM_W1T 0                           // [64 n][136 k] tf32 (kperm)
#define ESM_E1  (64 * 136)                  // [64][132] tf32 linear
#define ESM_E2  (ESM_E1 + 64 * 132)         // [64][66]
#define ESM_B1  (ESM_E2 + 64 * 66)
#define ESM_W2  (ESM_B1 + 64)
#define ESM_B2  (ESM_W2 + 128)
#define ESM_IDX (ESM_B2 + 4)                // srcs[64], dsts[64]
#define SMEM_EDGE_BYTES ((ESM_IDX + 128) * 4)

__global__ void __launch_bounds__(256) edge_mlp_kernel(
        const int* __restrict__ src, const int* __restrict__ dst,
        const float* __restrict__ W1, const float* __restrict__ b1,
        const float* __restrict__ W2, const float* __restrict__ b2,
        float* __restrict__ out) {
    extern __shared__ float sm_e[];
    uint32_t* W1t = (uint32_t*)(sm_e + ESM_W1T);
    uint32_t* e1u = (uint32_t*)(sm_e + ESM_E1);
    float* e2s = sm_e + ESM_E2;
    float* b1s = sm_e + ESM_B1;
    float* W2s = sm_e + ESM_W2;
    float* b2s = sm_e + ESM_B2;
    int*   srcs = (int*)(sm_e + ESM_IDX);
    int*   dsts = srcs + 64;

    int tid = threadIdx.x;
    int e0 = blockIdx.x * TS;
    int w = tid >> 5, lane = tid & 31;
    int g = lane >> 2, tig = lane & 3;
    int rg = w & 3, r0 = rg * 16;
    int ch = w >> 2, n0 = ch * 32;

    {
        int n = tid & 63, kb = tid >> 6;
#pragma unroll
        for (int j = 0; j < 32; j++) {
            int k = kb + j * 4;
            W1t[n * 136 + kperm(k)] = f2tf(W1[k * 64 + n]);
        }
    }
    if (tid < 64)  b1s[tid] = b1[tid];
    if (tid < 128) W2s[tid] = W2[tid];
    if (tid < 2)   b2s[tid] = b2[tid];
    if (tid < 64)  { srcs[tid] = src[e0 + tid]; dsts[tid] = dst[e0 + tid]; }
    __syncthreads();

    // ---- stage 1: gather + add + relu -> e1 (tf32, linear layout) ----
#pragma unroll
    for (int i = 0; i < 8; i++) {
        int idx = tid + i * 256;            // float4 units, 2048 total
        int r = idx >> 5, c4 = idx & 31;
        const float4 u = *reinterpret_cast<const float4*>(&g_pu[srcs[r] * HID + c4 * 4]);
        const float4 v = *reinterpret_cast<const float4*>(&g_pv[dsts[r] * HID + c4 * 4]);
        uint4 o;
        o.x = f2tf(fmaxf(u.x + v.x, 0.0f));
        o.y = f2tf(fmaxf(u.y + v.y, 0.0f));
        o.z = f2tf(fmaxf(u.z + v.z, 0.0f));
        o.w = f2tf(fmaxf(u.w + v.w, 0.0f));
        *reinterpret_cast<uint4*>(&e1u[r * 132 + c4 * 4]) = o;
    }
    __syncthreads();

    // ---- stage 2: [64,128] @ [128,64] via tf32 mma (paired B loads) ----
    float C[4][4];
#pragma unroll
    for (int nt = 0; nt < 4; nt++)
#pragma unroll
        for (int j = 0; j < 4; j++) C[nt][j] = 0.0f;

#pragma unroll
    for (int s = 0; s < 16; s++) {
        int kl = s * 8;
        uint32_t a0 = e1u[(r0 + g) * 132 + kl + tig];
        uint32_t a1 = e1u[(r0 + g + 8) * 132 + kl + tig];
        uint32_t a2 = e1u[(r0 + g) * 132 + kl + tig + 4];
        uint32_t a3 = e1u[(r0 + g + 8) * 132 + kl + tig + 4];
#pragma unroll
        for (int nt = 0; nt < 4; nt++) {
            int nn = n0 + nt * 8 + g;
            const uint2 bb = *reinterpret_cast<const uint2*>(
                &W1t[nn * 136 + kl + 2 * tig]);
            mma_tf32(C[nt], a0, a1, a2, a3, bb.x, bb.y);
        }
    }
#pragma unroll
    for (int nt = 0; nt < 4; nt++) {
        int col = n0 + nt * 8 + 2 * tig;
        e2s[(r0 + g) * 66 + col]     = fmaxf(C[nt][0] + b1s[col], 0.0f);
        e2s[(r0 + g) * 66 + col + 1] = fmaxf(C[nt][1] + b1s[col + 1], 0.0f);
        e2s[(r0 + g + 8) * 66 + col]     = fmaxf(C[nt][2] + b1s[col], 0.0f);
        e2s[(r0 + g + 8) * 66 + col + 1] = fmaxf(C[nt][3] + b1s[col + 1], 0.0f);
    }
    __syncthreads();

    // ---- stage 3: [64,64] @ [64,2] -> out, all 256 threads ----
    {
        int r = tid >> 2, sub = tid & 3, c = sub >> 1, kh = sub & 1;
        float s = 0.0f;
        const float* row = &e2s[r * 66 + kh * 32];
#pragma unroll
        for (int k = 0; k < 32; k++) s += row[k] * W2s[(kh * 32 + k) * 2 + c];
        s += __shfl_xor_sync(0xffffffffu, s, 1);
        if (kh == 0) out[(e0 + r) * 2 + c] = s + b2s[c];
    }
}

// ---------------------------------------------------------------------------
extern "C" void kernel_launch(void* const* d_in, const int* in_sizes, int n_in,
                              void* d_out, int out_size) {
    const float* x       = (const float*)d_in[0];
    const int*   src     = (const int*)d_in[1];
    const int*   dst     = (const int*)d_in[2];
    // d_in[3] snorm_n, d_in[4] snorm_e: all-ones, unused
    const float* W_embed = (const float*)d_in[5];
    const float* b_embed = (const float*)d_in[6];
    const float* W_conv  = (const float*)d_in[7];
    const float* b_conv  = (const float*)d_in[8];
    const float* W0      = (const float*)d_in[9];
    const float* b0      = (const float*)d_in[10];
    const float* W1      = (const float*)d_in[11];
    const float* b1      = (const float*)d_in[12];
    const float* W2      = (const float*)d_in[13];
    const float* b2      = (const float*)d_in[14];
    float* out = (float*)d_out;

    cudaFuncSetAttribute(edge_mlp_kernel,
                         cudaFuncAttributeMaxDynamicSharedMemorySize,
                         SMEM_EDGE_BYTES);
    cudaFuncSetAttribute(node_apply_kernel,
                         cudaFuncAttributeMaxDynamicSharedMemorySize,
                         NA_BYTES);
    cudaFuncSetAttribute(pre_edge_kernel,
                         cudaFuncAttributeMaxDynamicSharedMemorySize,
                         PE_BYTES);
    cudaFuncSetAttribute(embed_kernel,
                         cudaFuncAttributeMaxDynamicSharedMemorySize,
                         EM_BYTES);

    // CSR build (by dst)
    zero_cnt_kernel<<<(NN + 255) / 256, 256>>>();
    hist_kernel<<<(NE + 255) / 256, 256>>>(dst);
    scan1_kernel<<<NSBLK, 256>>>();
    scan2_kernel<<<1, 256>>>();
    scan3_kernel<<<NSBLK, 256>>>();
    fill_kernel<<<(NE + 255) / 256, 256>>>(src, dst);

    embed_kernel<<<(NN + 63) / 64, 256, EM_BYTES>>>(x, W_embed, b_embed);

    for (int l = 0; l < NLAYERS; l++) {
        agg_kernel<<<(NN * 32 + 255) / 256, 256>>>();
        node_apply_kernel<<<(NN + 127) / 128, 512, NA_BYTES>>>(W_conv, b_conv, l);
    }

    pre_edge_kernel<<<(NN + 63) / 64, 256, PE_BYTES>>>(W0, b0);
    edge_mlp_kernel<<<NTILES, 256, SMEM_EDGE_BYTES>>>(src, dst, W1, b1, W2, b2,
                                                      out);
}

// round 17
// speedup vs baseline: 1.0585x; 1.0042x over previous
#include <cuda_runtime.h>
#include <cuda_fp16.h>
#include <math.h>
#include <stdint.h>

#define NN 50000
#define NE 800000
#define IN_DIM 64
#define HID 128
#define NLAYERS 4
#define TS 64               // edges per tile in edge MLP
#define NTILES (NE / TS)    // 12500
#define NSBLK ((NN + 255) / 256)   // 196 scan blocks

// Persistent scratch (no allocations allowed)
__device__ float  g_h[NN * HID];      // node embeddings (fp32, exact path)
__device__ __half g_h16[NN * HID];    // fp16 shadow of h (agg gathers only)
__device__ float  g_mean[NN * HID];   // neighbor-mean (fp32)
__device__ float  g_pu[NN * HID];     // h @ W0_top + b0
__device__ float  g_pv[NN * HID];     // h @ W0_bot
__device__ int    g_cnt[NN];          // histogram / fill counters
__device__ int    g_row[NN + 1];      // CSR row offsets (by dst)
__device__ int    g_csr_src[NE];      // src node per CSR slot
__device__ int    g_bsum[NSBLK];      // scan block sums

// ---------------------------------------------------------------------------
__device__ __forceinline__ uint32_t f2tf(float x) {
    uint32_t r;
    asm("cvt.rna.tf32.f32 %0, %1;" : "=r"(r) : "f"(x));
    return r;
}

// fragment permutation: puts (k+tig, k+tig+4) adjacent for paired LDS.64
__device__ __forceinline__ int kperm(int k) {
    return (k & ~7) + ((k & 3) << 1) + ((k >> 2) & 1);
}

__device__ __forceinline__ void mma_tf32(float* c, uint32_t a0, uint32_t a1,
                                         uint32_t a2, uint32_t a3,
                                         uint32_t b0, uint32_t b1) {
    asm volatile(
        "mma.sync.aligned.m16n8k8.row.col.f32.tf32.tf32.f32 "
        "{%0,%1,%2,%3}, {%4,%5,%6,%7}, {%8,%9}, {%0,%1,%2,%3};\n"
        : "+f"(c[0]), "+f"(c[1]), "+f"(c[2]), "+f"(c[3])
        : "r"(a0), "r"(a1), "r"(a2), "r"(a3), "r"(b0), "r"(b1));
}

// ---------------------------------------------------------------------------
__global__ void __launch_bounds__(256) zero_cnt_kernel() {
    int i = blockIdx.x * blockDim.x + threadIdx.x;
    if (i < NN) g_cnt[i] = 0;
}

__global__ void __launch_bounds__(256) hist_kernel(const int* __restrict__ dst) {
    int e = blockIdx.x * blockDim.x + threadIdx.x;
    if (e < NE) atomicAdd(&g_cnt[dst[e]], 1);
}

// parallel scan, 3 stages
__global__ void __launch_bounds__(256) scan1_kernel() {
    __shared__ int sh[256];
    int t = threadIdx.x;
    int i = blockIdx.x * 256 + t;
    sh[t] = (i < NN) ? g_cnt[i] : 0;
    __syncthreads();
    for (int off = 128; off > 0; off >>= 1) {
        if (t < off) sh[t] += sh[t + off];
        __syncthreads();
    }
    if (t == 0) g_bsum[blockIdx.x] = sh[0];
}

__global__ void __launch_bounds__(256) scan2_kernel() {
    __shared__ int sh[256];
    int t = threadIdx.x;
    sh[t] = (t < NSBLK) ? g_bsum[t] : 0;
    __syncthreads();
    for (int off = 1; off < 256; off <<= 1) {
        int u = sh[t];
        if (t >= off) u += sh[t - off];
        __syncthreads();
        sh[t] = u;
        __syncthreads();
    }
    if (t < NSBLK) g_bsum[t] = (t == 0) ? 0 : sh[t - 1];
    if (t == 0) g_row[NN] = NE;
}

__global__ void __launch_bounds__(256) scan3_kernel() {
    __shared__ int sh[256];
    int t = threadIdx.x;
    int i = blockIdx.x * 256 + t;
    int v = (i < NN) ? g_cnt[i] : 0;
    sh[t] = v;
    __syncthreads();
    for (int off = 1; off < 256; off <<= 1) {
        int u = sh[t];
        if (t >= off) u += sh[t - off];
        __syncthreads();
        sh[t] = u;
        __syncthreads();
    }
    if (i < NN) {
        g_row[i] = sh[t] - v + g_bsum[blockIdx.x];
        g_cnt[i] = 0;
    }
}

__global__ void __launch_bounds__(256) fill_kernel(const int* __restrict__ src,
                                                   const int* __restrict__ dst) {
    int e = blockIdx.x * blockDim.x + threadIdx.x;
    if (e >= NE) return;
    int d = dst[e];
    int pos = g_row[d] + atomicAdd(&g_cnt[d], 1);
    g_csr_src[pos] = src[e];
}

// ---------------------------------------------------------------------------
// warp per node: mean of neighbor rows gathered from fp16 shadow (8B/lane),
// idx via coalesced LDG + shfl, 4 rows in flight.
__global__ void __launch_bounds__(256) agg_kernel() {
    int w = (blockIdx.x * 256 + threadIdx.x) >> 5;
    int lane = threadIdx.x & 31;
    if (w >= NN) return;
    int s0 = g_row[w], s1 = g_row[w + 1];
    float4 a = {0.f, 0.f, 0.f, 0.f};
    float4 b = {0.f, 0.f, 0.f, 0.f};
    float4 c = {0.f, 0.f, 0.f, 0.f};
    float4 d = {0.f, 0.f, 0.f, 0.f};
    for (int base = s0; base < s1; base += 32) {
        int n = s1 - base;
        int lim = (n < 32) ? n : 32;
        int myidx = 0;
        if (lane < lim) myidx = __ldg(&g_csr_src[base + lane]);
        int j = 0;
        for (; j + 3 < lim; j += 4) {
            int na = __shfl_sync(0xffffffffu, myidx, j);
            int nb = __shfl_sync(0xffffffffu, myidx, j + 1);
            int nc = __shfl_sync(0xffffffffu, myidx, j + 2);
            int nd = __shfl_sync(0xffffffffu, myidx, j + 3);
            uint2 ua = *reinterpret_cast<const uint2*>(&g_h16[na * HID + lane * 4]);
            uint2 ub = *reinterpret_cast<const uint2*>(&g_h16[nb * HID + lane * 4]);
            uint2 uc = *reinterpret_cast<const uint2*>(&g_h16[nc * HID + lane * 4]);
            uint2 ud = *reinterpret_cast<const uint2*>(&g_h16[nd * HID + lane * 4]);
            float2 f;
            f = __half22float2(*reinterpret_cast<__half2*>(&ua.x)); a.x += f.x; a.y += f.y;
            f = __half22float2(*reinterpret_cast<__half2*>(&ua.y)); a.z += f.x; a.w += f.y;
            f = __half22float2(*reinterpret_cast<__half2*>(&ub.x)); b.x += f.x; b.y += f.y;
            f = __half22float2(*reinterpret_cast<__half2*>(&ub.y)); b.z += f.x; b.w += f.y;
            f = __half22float2(*reinterpret_cast<__half2*>(&uc.x)); c.x += f.x; c.y += f.y;
            f = __half22float2(*reinterpret_cast<__half2*>(&uc.y)); c.z += f.x; c.w += f.y;
            f = __half22float2(*reinterpret_cast<__half2*>(&ud.x)); d.x += f.x; d.y += f.y;
            f = __half22float2(*reinterpret_cast<__half2*>(&ud.y)); d.z += f.x; d.w += f.y;
        }
        for (; j < lim; j++) {
            int na = __shfl_sync(0xffffffffu, myidx, j);
            uint2 ua = *reinterpret_cast<const uint2*>(&g_h16[na * HID + lane * 4]);
            float2 f;
            f = __half22float2(*reinterpret_cast<__half2*>(&ua.x)); a.x += f.x; a.y += f.y;
            f = __half22float2(*reinterpret_cast<__half2*>(&ua.y)); a.z += f.x; a.w += f.y;
        }
    }
    a.x += b.x + c.x + d.x;
    a.y += b.y + c.y + d.y;
    a.z += b.z + c.z + d.z;
    a.w += b.w + c.w + d.w;
    float inv = 1.0f / fmaxf((float)(s1 - s0), 1.0f);
    float4 o = {a.x * inv, a.y * inv, a.z * inv, a.w * inv};
    *reinterpret_cast<float4*>(&g_mean[w * HID + lane * 4]) = o;
}

// ---------------------------------------------------------------------------
// embed via tf32 mma (paired-LDS layout): h = x @ W_embed + b, 64 rows/block.
#define EM_A    0                          // [64][72] tf32 (kperm)
#define EM_BT   (64 * 72)                  // [128][72] tf32 (kperm)
#define EM_BIAS (EM_BT + 128 * 72)
#define EM_FLOATS (EM_BIAS + 128)
#define EM_BYTES (EM_FLOATS * 4)

__global__ void __launch_bounds__(256) embed_kernel(const float* __restrict__ x,
                                                    const float* __restrict__ W,
                                                    const float* __restrict__ b) {
    extern __shared__ float sm_em[];
    uint32_t* A_s  = (uint32_t*)(sm_em + EM_A);
    uint32_t* Bt   = (uint32_t*)(sm_em + EM_BT);
    float*    bias = sm_em + EM_BIAS;

    int tid = threadIdx.x;
    int w = tid >> 5, lane = tid & 31;
    int g = lane >> 2, tig = lane & 3;
    int rg = w & 3, r0 = rg * 16;
    int ch = w >> 2, n0 = ch * 64;
    int row0 = blockIdx.x * 64;

    if (tid < 128) bias[tid] = b[tid];

#pragma unroll
    for (int i = 0; i < 16; i++) {
        int idx = tid + i * 256;
        int r = idx >> 6, k = idx & 63;
        int row = row0 + r;
        A_s[r * 72 + kperm(k)] = f2tf((row < NN) ? x[row * IN_DIM + k] : 0.0f);
    }
    {
        int c = tid & 127, kb = tid >> 7;
#pragma unroll
        for (int j = 0; j < 32; j++) {
            int k = kb * 32 + j;
            Bt[c * 72 + kperm(k)] = f2tf(W[k * HID + c]);
        }
    }
    __syncthreads();

    float C[8][4];
#pragma unroll
    for (int nt = 0; nt < 8; nt++)
#pragma unroll
        for (int j = 0; j < 4; j++) C[nt][j] = 0.0f;

#pragma unroll
    for (int s = 0; s < 8; s++) {
        int kl = s * 8;
        const uint2 aA = *reinterpret_cast<const uint2*>(&A_s[(r0 + g) * 72 + kl + 2 * tig]);
        const uint2 aB = *reinterpret_cast<const uint2*>(&A_s[(r0 + g + 8) * 72 + kl + 2 * tig]);
#pragma unroll
        for (int nt = 0; nt < 8; nt++) {
            int nn = n0 + nt * 8 + g;
            const uint2 bb = *reinterpret_cast<const uint2*>(&Bt[nn * 72 + kl + 2 * tig]);
            mma_tf32(C[nt], aA.x, aB.x, aA.y, aB.y, bb.x, bb.y);
        }
    }

    int grow0 = row0 + r0 + g;
    int grow1 = grow0 + 8;
    if (grow0 < NN)
#pragma unroll
        for (int nt = 0; nt < 8; nt++) {
            int col = n0 + nt * 8 + 2 * tig;
            float2 o = {C[nt][0] + bias[col], C[nt][1] + bias[col + 1]};
            *reinterpret_cast<float2*>(&g_h[grow0 * HID + col]) = o;
            *reinterpret_cast<__half2*>(&g_h16[grow0 * HID + col]) =
                __floats2half2_rn(o.x, o.y);
        }
    if (grow1 < NN)
#pragma unroll
        for (int nt = 0; nt < 8; nt++) {
            int col = n0 + nt * 8 + 2 * tig;
            float2 o = {C[nt][2] + bias[col], C[nt][3] + bias[col + 1]};
            *reinterpret_cast<float2*>(&g_h[grow1 * HID + col]) = o;
            *reinterpret_cast<__half2*>(&g_h16[grow1 * HID + col]) =
                __floats2half2_rn(o.x, o.y);
        }
}

// ---------------------------------------------------------------------------
// node_apply via tf32 mma (paired-LDS layout): 128 rows/block, 512 threads.
#define NA_A    0                          // [128][72] u32 (kperm)
#define NA_BT   (128 * 72)                 // [128][72] u32 (kperm)
#define NA_RQ   (NA_BT + 128 * 72)         // [2][128]
#define NA_BIAS (NA_RQ + 256)
#define NA_FLOATS (NA_BIAS + 128)
#define NA_BYTES (NA_FLOATS * 4)

__global__ void __launch_bounds__(512) node_apply_kernel(const float* __restrict__ Wc,
                                                         const float* __restrict__ bc,
                                                         int layer) {
    extern __shared__ float sm_na[];
    uint32_t* A_s  = (uint32_t*)(sm_na + NA_A);
    uint32_t* Bt   = (uint32_t*)(sm_na + NA_BT);
    float*    rowsq = sm_na + NA_RQ;
    float*    bias  = sm_na + NA_BIAS;

    const float* W = Wc + layer * (2 * HID) * HID;
    const float* b = bc + layer * HID;

    int tid = threadIdx.x;
    int w = tid >> 5, lane = tid & 31;
    int g = lane >> 2, tig = lane & 3;
    int rg = w & 7, r0 = rg * 16;
    int ch = w >> 3, n0 = ch * 64;
    int row0 = blockIdx.x * 128;

    if (tid < 128) bias[tid] = b[tid];

    float C[8][4];
#pragma unroll
    for (int nt = 0; nt < 8; nt++)
#pragma unroll
        for (int j = 0; j < 4; j++) C[nt][j] = 0.0f;

    for (int kk = 0; kk < 2 * HID; kk += 64) {
        __syncthreads();
#pragma unroll
        for (int i = 0; i < 16; i++) {
            int idx = tid + i * 512;
            int r = idx >> 6, k = idx & 63;
            int gk = kk + k;
            int row = row0 + r;
            float v = 0.0f;
            if (row < NN)
                v = (gk < HID) ? g_h[row * HID + gk] : g_mean[row * HID + gk - HID];
            A_s[r * 72 + kperm(k)] = f2tf(v);
        }
        {
            int c = tid & 127, kb = tid >> 7;   // kb 0..3
#pragma unroll
            for (int j = 0; j < 16; j++) {
                int k = kb * 16 + j;
                Bt[c * 72 + kperm(k)] = f2tf(W[(kk + k) * HID + c]);
            }
        }
        __syncthreads();

#pragma unroll
        for (int s = 0; s < 8; s++) {
            int kl = s * 8;
            const uint2 aA = *reinterpret_cast<const uint2*>(&A_s[(r0 + g) * 72 + kl + 2 * tig]);
            const uint2 aB = *reinterpret_cast<const uint2*>(&A_s[(r0 + g + 8) * 72 + kl + 2 * tig]);
#pragma unroll
            for (int nt = 0; nt < 8; nt++) {
                int nn = n0 + nt * 8 + g;
                const uint2 bb = *reinterpret_cast<const uint2*>(&Bt[nn * 72 + kl + 2 * tig]);
                mma_tf32(C[nt], aA.x, aB.x, aA.y, aB.y, bb.x, bb.y);
            }
        }
    }

    float ss0 = 0.0f, ss1 = 0.0f;
#pragma unroll
    for (int nt = 0; nt < 8; nt++) {
        int col = n0 + nt * 8 + 2 * tig;
        C[nt][0] += bias[col];
        C[nt][1] += bias[col + 1];
        C[nt][2] += bias[col];
        C[nt][3] += bias[col + 1];
        ss0 += C[nt][0] * C[nt][0] + C[nt][1] * C[nt][1];
        ss1 += C[nt][2] * C[nt][2] + C[nt][3] * C[nt][3];
    }
    ss0 += __shfl_xor_sync(0xffffffffu, ss0, 1);
    ss0 += __shfl_xor_sync(0xffffffffu, ss0, 2);
    ss1 += __shfl_xor_sync(0xffffffffu, ss1, 1);
    ss1 += __shfl_xor_sync(0xffffffffu, ss1, 2);
    if (tig == 0) {
        rowsq[ch * 128 + r0 + g] = ss0;
        rowsq[ch * 128 + r0 + g + 8] = ss1;
    }
    __syncthreads();
    float t0 = rowsq[r0 + g] + rowsq[128 + r0 + g];
    float t1 = rowsq[r0 + g + 8] + rowsq[128 + r0 + g + 8];
    float inv0 = 1.0f / fmaxf(sqrtf(t0), 1e-12f);
    float inv1 = 1.0f / fmaxf(sqrtf(t1), 1e-12f);

    int grow0 = row0 + r0 + g;
    int grow1 = grow0 + 8;
    if (grow0 < NN) {
#pragma unroll
        for (int nt = 0; nt < 8; nt++) {
            int col = n0 + nt * 8 + 2 * tig;
            float2 old = *reinterpret_cast<float2*>(&g_h[grow0 * HID + col]);
            old.x += fmaxf(C[nt][0] * inv0, 0.0f);
            old.y += fmaxf(C[nt][1] * inv0, 0.0f);
            *reinterpret_cast<float2*>(&g_h[grow0 * HID + col]) = old;
            *reinterpret_cast<__half2*>(&g_h16[grow0 * HID + col]) =
                __floats2half2_rn(old.x, old.y);
        }
    }
    if (grow1 < NN) {
#pragma unroll
        for (int nt = 0; nt < 8; nt++) {
            int col = n0 + nt * 8 + 2 * tig;
            float2 old = *reinterpret_cast<float2*>(&g_h[grow1 * HID + col]);
            old.x += fmaxf(C[nt][2] * inv1, 0.0f);
            old.y += fmaxf(C[nt][3] * inv1, 0.0f);
            *reinterpret_cast<float2*>(&g_h[grow1 * HID + col]) = old;
            *reinterpret_cast<__half2*>(&g_h16[grow1 * HID + col]) =
                __floats2half2_rn(old.x, old.y);
        }
    }
}

// ---------------------------------------------------------------------------
// pre_edge via tf32 mma (paired-LDS layout)
#define PE_A    0                          // [64][136] tf32 (kperm in 8-groups)
#define PE_BT   (64 * 136)                 // [128][72] tf32 (kperm)
#define PE_BIAS (PE_BT + 128 * 72)
#define PE_FLOATS (PE_BIAS + 128)
#define PE_BYTES (PE_FLOATS * 4)

__global__ void __launch_bounds__(256) pre_edge_kernel(const float* __restrict__ W0,
                                                       const float* __restrict__ b0) {
    extern __shared__ float sm_pe[];
    uint32_t* A_s  = (uint32_t*)(sm_pe + PE_A);
    uint32_t* Bt   = (uint32_t*)(sm_pe + PE_BT);
    float*    bias = sm_pe + PE_BIAS;

    int tid = threadIdx.x;
    int w = tid >> 5, lane = tid & 31;
    int g = lane >> 2, tig = lane & 3;
    int rg = w & 3, r0 = rg * 16;
    int ch = w >> 2, n0 = ch * 64;
    int row0 = blockIdx.x * 64;

    if (tid < 128) bias[tid] = b0[tid];

#pragma unroll
    for (int i = 0; i < 32; i++) {
        int idx = tid + i * 256;
        int r = idx >> 7, k = idx & 127;
        int row = row0 + r;
        A_s[r * 136 + kperm(k)] = f2tf((row < NN) ? g_h[row * HID + k] : 0.0f);
    }

#pragma unroll
    for (int half = 0; half < 2; half++) {
        float C[8][4];
#pragma unroll
        for (int nt = 0; nt < 8; nt++)
#pragma unroll
            for (int j = 0; j < 4; j++) C[nt][j] = 0.0f;

        for (int kk = 0; kk < HID; kk += 64) {
            __syncthreads();
            {
                int c = tid & 127, kb = tid >> 7;
#pragma unroll
                for (int j = 0; j < 32; j++) {
                    int k = kb * 32 + j;
                    Bt[c * 72 + kperm(k)] = f2tf(W0[(half * HID + kk + k) * HID + c]);
                }
            }
            __syncthreads();
#pragma unroll
            for (int s = 0; s < 8; s++) {
                int kl = s * 8;
                const uint2 aA = *reinterpret_cast<const uint2*>(
                    &A_s[(r0 + g) * 136 + kk + kl + 2 * tig]);
                const uint2 aB = *reinterpret_cast<const uint2*>(
                    &A_s[(r0 + g + 8) * 136 + kk + kl + 2 * tig]);
#pragma unroll
                for (int nt = 0; nt < 8; nt++) {
                    int nn = n0 + nt * 8 + g;
                    const uint2 bb = *reinterpret_cast<const uint2*>(
                        &Bt[nn * 72 + kl + 2 * tig]);
                    mma_tf32(C[nt], aA.x, aB.x, aA.y, aB.y, bb.x, bb.y);
                }
            }
        }

        int grow0 = row0 + r0 + g;
        int grow1 = grow0 + 8;
        if (half == 0) {
            if (grow0 < NN)
#pragma unroll
                for (int nt = 0; nt < 8; nt++) {
                    int col = n0 + nt * 8 + 2 * tig;
                    float2 o = {C[nt][0] + bias[col], C[nt][1] + bias[col + 1]};
                    *reinterpret_cast<float2*>(&g_pu[grow0 * HID + col]) = o;
                }
            if (grow1 < NN)
#pragma unroll
                for (int nt = 0; nt < 8; nt++) {
                    int col = n0 + nt * 8 + 2 * tig;
                    float2 o = {C[nt][2] + bias[col], C[nt][3] + bias[col + 1]};
                    *reinterpret_cast<float2*>(&g_pu[grow1 * HID + col]) = o;
                }
        } else {
            if (grow0 < NN)
#pragma unroll
                for (int nt = 0; nt < 8; nt++) {
                    int col = n0 + nt * 8 + 2 * tig;
                    float2 o = {C[nt][0], C[nt][1]};
                    *reinterpret_cast<float2*>(&g_pv[grow0 * HID + col]) = o;
                }
            if (grow1 < NN)
#pragma unroll
                for (int nt = 0; nt < 8; nt++) {
                    int col = n0 + nt * 8 + 2 * tig;
                    float2 o = {C[nt][2], C[nt][3]};
                    *reinterpret_cast<float2*>(&g_pv[grow1 * HID + col]) = o;
                }
        }
    }
}

// ---------------------------------------------------------------------------
// Edge readout: 2 tiles of 64 edges per block (W1t/W2/bias loaded once).
// e1 = relu(pu[src]+pv[dst]); e2 = relu(e1@W1+b1) tf32 mma; out = e2@W2+b2.
#define ESM_W1T 0                           // [64 n][136 k] tf32 (kperm)
#define ESM_E1  (64 * 136)                  // [64][132] tf32 linear
#define ESM_E2  (ESM_E1 + 64 * 132)         // [64][66]
#define ESM_B1  (ESM_E2 + 64 * 66)
#define ESM_W2  (ESM_B1 + 64)
#define ESM_B2  (ESM_W2 + 128)
#define ESM_IDX (ESM_B2 + 4)                // srcs[64], dsts[64]
#define SMEM_EDGE_BYTES ((ESM_IDX + 128) * 4)

__global__ void __launch_bounds__(256) edge_mlp_kernel(
        const int* __restrict__ src, const int* __restrict__ dst,
        const float* __restrict__ W1, const float* __restrict__ b1,
        const float* __restrict__ W2, const float* __restrict__ b2,
        float* __restrict__ out) {
    extern __shared__ float sm_e[];
    uint32_t* W1t = (uint32_t*)(sm_e + ESM_W1T);
    uint32_t* e1u = (uint32_t*)(sm_e + ESM_E1);
    float* e2s = sm_e + ESM_E2;
    float* b1s = sm_e + ESM_B1;
    float* W2s = sm_e + ESM_W2;
    float* b2s = sm_e + ESM_B2;
    int*   srcs = (int*)(sm_e + ESM_IDX);
    int*   dsts = srcs + 64;

    int tid = threadIdx.x;
    int w = tid >> 5, lane = tid & 31;
    int g = lane >> 2, tig = lane & 3;
    int rg = w & 3, r0 = rg * 16;
    int ch = w >> 2, n0 = ch * 32;

    {
        int n = tid & 63, kb = tid >> 6;
#pragma unroll
        for (int j = 0; j < 32; j++) {
            int k = kb + j * 4;
            W1t[n * 136 + kperm(k)] = f2tf(W1[k * 64 + n]);
        }
    }
    if (tid < 64)  b1s[tid] = b1[tid];
    if (tid < 128) W2s[tid] = W2[tid];
    if (tid < 2)   b2s[tid] = b2[tid];

#pragma unroll
    for (int t = 0; t < 2; t++) {
        int e0 = (blockIdx.x * 2 + t) * TS;
        __syncthreads();   // weights ready (t=0) / prev tile fully consumed
        if (tid < 64) { srcs[tid] = src[e0 + tid]; dsts[tid] = dst[e0 + tid]; }
        __syncthreads();

        // ---- stage 1: gather + add + relu -> e1 (tf32, linear layout) ----
#pragma unroll
        for (int i = 0; i < 8; i++) {
            int idx = tid + i * 256;            // float4 units, 2048 total
            int r = idx >> 5, c4 = idx & 31;
            const float4 u = *reinterpret_cast<const float4*>(&g_pu[srcs[r] * HID + c4 * 4]);
            const float4 v = *reinterpret_cast<const float4*>(&g_pv[dsts[r] * HID + c4 * 4]);
            uint4 o;
            o.x = f2tf(fmaxf(u.x + v.x, 0.0f));
            o.y = f2tf(fmaxf(u.y + v.y, 0.0f));
            o.z = f2tf(fmaxf(u.z + v.z, 0.0f));
            o.w = f2tf(fmaxf(u.w + v.w, 0.0f));
            *reinterpret_cast<uint4*>(&e1u[r * 132 + c4 * 4]) = o;
        }
        __syncthreads();

        // ---- stage 2: [64,128] @ [128,64] via tf32 mma (paired B loads) ----
        float C[4][4];
#pragma unroll
        for (int nt = 0; nt < 4; nt++)
#pragma unroll
            for (int j = 0; j < 4; j++) C[nt][j] = 0.0f;

#pragma unroll
        for (int s = 0; s < 16; s++) {
            int kl = s * 8;
            uint32_t a0 = e1u[(r0 + g) * 132 + kl + tig];
            uint32_t a1 = e1u[(r0 + g + 8) * 132 + kl + tig];
            uint32_t a2 = e1u[(r0 + g) * 132 + kl + tig + 4];
            uint32_t a3 = e1u[(r0 + g + 8) * 132 + kl + tig + 4];
#pragma unroll
            for (int nt = 0; nt < 4; nt++) {
                int nn = n0 + nt * 8 + g;
                const uint2 bb = *reinterpret_cast<const uint2*>(
                    &W1t[nn * 136 + kl + 2 * tig]);
                mma_tf32(C[nt], a0, a1, a2, a3, bb.x, bb.y);
            }
        }
#pragma unroll
        for (int nt = 0; nt < 4; nt++) {
            int col = n0 + nt * 8 + 2 * tig;
            e2s[(r0 + g) * 66 + col]     = fmaxf(C[nt][0] + b1s[col], 0.0f);
            e2s[(r0 + g) * 66 + col + 1] = fmaxf(C[nt][1] + b1s[col + 1], 0.0f);
            e2s[(r0 + g + 8) * 66 + col]     = fmaxf(C[nt][2] + b1s[col], 0.0f);
            e2s[(r0 + g + 8) * 66 + col + 1] = fmaxf(C[nt][3] + b1s[col + 1], 0.0f);
        }
        __syncthreads();

        // ---- stage 3: [64,64] @ [64,2] -> out, all 256 threads ----
        {
            int r = tid >> 2, sub = tid & 3, c = sub >> 1, kh = sub & 1;
            float s = 0.0f;
            const float* row = &e2s[r * 66 + kh * 32];
#pragma unroll
            for (int k = 0; k < 32; k++) s += row[k] * W2s[(kh * 32 + k) * 2 + c];
            s += __shfl_xor_sync(0xffffffffu, s, 1);
            if (kh == 0) out[(e0 + r) * 2 + c] = s + b2s[c];
        }
    }
}

// ---------------------------------------------------------------------------
extern "C" void kernel_launch(void* const* d_in, const int* in_sizes, int n_in,
                              void* d_out, int out_size) {
    const float* x       = (const float*)d_in[0];
    const int*   src     = (const int*)d_in[1];
    const int*   dst     = (const int*)d_in[2];
    // d_in[3] snorm_n, d_in[4] snorm_e: all-ones, unused
    const float* W_embed = (const float*)d_in[5];
    const float* b_embed = (const float*)d_in[6];
    const float* W_conv  = (const float*)d_in[7];
    const float* b_conv  = (const float*)d_in[8];
    const float* W0      = (const float*)d_in[9];
    const float* b0      = (const float*)d_in[10];
    const float* W1      = (const float*)d_in[11];
    const float* b1      = (const float*)d_in[12];
    const float* W2      = (const float*)d_in[13];
    const float* b2      = (const float*)d_in[14];
    float* out = (float*)d_out;

    cudaFuncSetAttribute(edge_mlp_kernel,
                         cudaFuncAttributeMaxDynamicSharedMemorySize,
                         SMEM_EDGE_BYTES);
    cudaFuncSetAttribute(node_apply_kernel,
                         cudaFuncAttributeMaxDynamicSharedMemorySize,
                         NA_BYTES);
    cudaFuncSetAttribute(pre_edge_kernel,
                         cudaFuncAttributeMaxDynamicSharedMemorySize,
                         PE_BYTES);
    cudaFuncSetAttribute(embed_kernel,
                         cudaFuncAttributeMaxDynamicSharedMemorySize,
                         EM_BYTES);

    // CSR build (by dst)
    zero_cnt_kernel<<<(NN + 255) / 256, 256>>>();
    hist_kernel<<<(NE + 255) / 256, 256>>>(dst);
    scan1_kernel<<<NSBLK, 256>>>();
    scan2_kernel<<<1, 256>>>();
    scan3_kernel<<<NSBLK, 256>>>();
    fill_kernel<<<(NE + 255) / 256, 256>>>(src, dst);

    embed_kernel<<<(NN + 63) / 64, 256, EM_BYTES>>>(x, W_embed, b_embed);

    for (int l = 0; l < NLAYERS; l++) {
        agg_kernel<<<(NN * 32 + 255) / 256, 256>>>();
        node_apply_kernel<<<(NN + 127) / 128, 512, NA_BYTES>>>(W_conv, b_conv, l);
    }

    pre_edge_kernel<<<(NN + 63) / 64, 256, PE_BYTES>>>(W0, b0);
    edge_mlp_kernel<<<NTILES / 2, 256, SMEM_EDGE_BYTES>>>(src, dst, W1, b1, W2,
                                                          b2, out);
}